// round 11
// baseline (speedup 1.0000x reference)
#include <cuda_runtime.h>

// ---------------------------------------------------------------------------
// GCN_63694364999884 — rank-8 commuted aggregation; dis factored into source
// pre-scaling; bare-int CSR scatter (8-edge MLP); k-split smem-tiled t1
// merged with scan pass 2. 6 launches.
// ---------------------------------------------------------------------------

#define NMAX 50000
#define EMAX 1600000
#define SCAN_B 1024
#define NSCANB ((NMAX + SCAN_B - 1) / SCAN_B)   // 49

__device__ int   g_deg [NMAX];          // zeroed at end of k_out (self-restoring)
__device__ int   g_off [NMAX];
__device__ int   g_cur [NMAX];          // after scatter: end offsets
__device__ int   g_bsum[NSCANB];
__device__ float g_dis [NMAX];
__device__ float g_embW[3 * 32];        // zeroed at end of prep block
__device__ __align__(16) float g_W1A [128 * 8];
__device__ __align__(16) float g_embWA[3 * 8];
__device__ __align__(16) float g_cA1[8];
__device__ __align__(16) float g_cA2[8];
__device__ __align__(16) float g_t1[NMAX * 8];   // dis[i] * (x@W1A + embWA[dom])
__device__ __align__(16) float g_t2[NMAX * 8];   // dis[i] * (hW2 @ A2)
__device__ int   g_eSrc[EMAX];                   // src indices bucketed by dst

// ---------------------------------------------------------------------------
// Launch 1: blocks [0,32): embW = emb @ W1[:4096]; rest: degree count, 8 e/thr.
__global__ void k_pre(const int* __restrict__ dst,
                      const float* __restrict__ emb,
                      const float* __restrict__ W1, int E) {
    if (blockIdx.x < 32) {
        __shared__ float part[8][3][32];
        int col = threadIdx.x & 31;
        int w   = threadIdx.x >> 5;
        int k0  = blockIdx.x * 128 + w * 16;
        float a0 = 0.f, a1 = 0.f, a2 = 0.f;
        #pragma unroll 4
        for (int i = 0; i < 16; ++i) {
            int k = k0 + i;
            float wv = W1[k * 32 + col];
            a0 = fmaf(emb[k],        wv, a0);
            a1 = fmaf(emb[4096 + k], wv, a1);
            a2 = fmaf(emb[8192 + k], wv, a2);
        }
        part[w][0][col] = a0; part[w][1][col] = a1; part[w][2][col] = a2;
        __syncthreads();
        if (threadIdx.x < 96) {
            int d = threadIdx.x >> 5, c = threadIdx.x & 31;
            float s = 0.f;
            #pragma unroll
            for (int ww = 0; ww < 8; ++ww) s += part[ww][d][c];
            atomicAdd(&g_embW[d * 32 + c], s);
        }
    } else {
        int e = ((blockIdx.x - 32) * blockDim.x + threadIdx.x) * 8;
        if (e + 8 <= E && (E & 7) == 0) {
            int4 da = *reinterpret_cast<const int4*>(dst + e);
            int4 db = *reinterpret_cast<const int4*>(dst + e + 4);
            atomicAdd(&g_deg[da.x], 1); atomicAdd(&g_deg[da.y], 1);
            atomicAdd(&g_deg[da.z], 1); atomicAdd(&g_deg[da.w], 1);
            atomicAdd(&g_deg[db.x], 1); atomicAdd(&g_deg[db.y], 1);
            atomicAdd(&g_deg[db.z], 1); atomicAdd(&g_deg[db.w], 1);
        } else {
            int ee = min(e + 8, E);
            for (; e < ee; ++e) atomicAdd(&g_deg[dst[e]], 1);
        }
    }
}

// ---------------------------------------------------------------------------
// Launch 2: blocks [0,nbScan): per-block exclusive scan of deg + dis.
//           last block: prep (W1A, embWA, cA1, cA2) + embW reset.
__global__ void __launch_bounds__(SCAN_B) k_scan1_prep(
        const float* __restrict__ W1, const float* __restrict__ A1,
        const float* __restrict__ b1, const float* __restrict__ A2,
        const float* __restrict__ b2, int n) {
    if (blockIdx.x + 1 < gridDim.x) {
        __shared__ int wsum[32];
        int i = blockIdx.x * SCAN_B + threadIdx.x;
        int lane = threadIdx.x & 31, w = threadIdx.x >> 5;
        int v = (i < n) ? g_deg[i] : 0;
        if (i < n) g_dis[i] = rsqrtf((float)v + 1.0f);
        int s = v;
        #pragma unroll
        for (int o = 1; o < 32; o <<= 1) {
            int t = __shfl_up_sync(0xFFFFFFFFu, s, o);
            if (lane >= o) s += t;
        }
        if (lane == 31) wsum[w] = s;
        __syncthreads();
        if (w == 0) {
            int ws = wsum[lane];
            #pragma unroll
            for (int o = 1; o < 32; o <<= 1) {
                int t = __shfl_up_sync(0xFFFFFFFFu, ws, o);
                if (lane >= o) ws += t;
            }
            wsum[lane] = ws;
        }
        __syncthreads();
        int pre = (w > 0) ? wsum[w - 1] : 0;
        int incl = s + pre;
        if (i < n) g_off[i] = incl - v;
        if (threadIdx.x == SCAN_B - 1) g_bsum[blockIdx.x] = incl;
    } else {
        __shared__ float sA1[256];
        int tid = threadIdx.x;
        if (tid < 256) sA1[tid] = A1[tid];
        __syncthreads();
        {   // W1A[k][r], 1024 threads
            int k = tid >> 3, r = tid & 7;
            float acc = 0.f;
            #pragma unroll
            for (int j = 0; j < 32; ++j)
                acc = fmaf(W1[(4096 + k) * 32 + j], sA1[j * 8 + r], acc);
            g_W1A[tid] = acc;
        }
        if (tid < 24) {
            int d = tid >> 3, r = tid & 7;
            float acc = 0.f;
            #pragma unroll
            for (int j = 0; j < 32; ++j)
                acc = fmaf(g_embW[d * 32 + j], sA1[j * 8 + r], acc);
            g_embWA[tid] = acc;
        } else if (tid < 32) {
            int r = tid - 24;
            float acc = 0.f;
            #pragma unroll
            for (int j = 0; j < 32; ++j)
                acc = fmaf(b1[j], sA1[j * 8 + r], acc);
            g_cA1[r] = acc;
        } else if (tid < 40) {
            int r = tid - 32;
            float acc = 0.f;
            #pragma unroll
            for (int c = 0; c < 5; ++c)
                acc = fmaf(b2[c], A2[c * 8 + r], acc);
            g_cA2[r] = acc;
        }
        __syncthreads();
        if (tid < 96) g_embW[tid] = 0.0f;   // restore for next call
    }
}

// ---------------------------------------------------------------------------
// Launch 3 (merged): blocks [0,nbS2): scan pass 2 (256 nodes/block, block
// prefix re-derived from g_bsum). blocks [nbS2,..): t1 GEMM, k-split
// across two 128-thread halves over 128 nodes.
__global__ void __launch_bounds__(256) k_scan2_t1(
        const float* __restrict__ x, const int* __restrict__ dom,
        int n, int nbS2) {
    int tid = threadIdx.x;
    if ((int)blockIdx.x < nbS2) {
        __shared__ int sred[2];
        int top = blockIdx.x >> 2;            // bsum entries fully before this block
        if (tid < 64) {
            int v = (tid < top) ? g_bsum[tid] : 0;   // top <= 48 < 64
            #pragma unroll
            for (int o = 16; o > 0; o >>= 1)
                v += __shfl_down_sync(0xFFFFFFFFu, v, o);
            if ((tid & 31) == 0) sred[tid >> 5] = v;
        }
        __syncthreads();
        int bpre = sred[0] + sred[1];
        int i = blockIdx.x * 256 + tid;
        if (i < n) {
            int o = g_off[i] + bpre;
            g_off[i] = o;
            g_cur[i] = o;
        }
        return;
    }
    // ---- t1 part ----
    __shared__ float  sx[2][128 * 33];       // 33.8 KB (one buffer per k-half)
    __shared__ float4 sWlo[128], sWhi[128];  // 4 KB
    __shared__ float  sE[24];
    __shared__ float4 sPart[256];            // upper-half partials, 4 KB

    int half = tid >> 7;          // 0: k 0-63,  1: k 64-127
    int lt   = tid & 127;
    if (tid < 128) {
        const float4* W4 = reinterpret_cast<const float4*>(g_W1A);
        sWlo[tid] = W4[tid * 2];
        sWhi[tid] = W4[tid * 2 + 1];
    }
    if (tid < 24) sE[tid] = g_embWA[tid];

    int base = (blockIdx.x - nbS2) * 128;
    float4 a03 = make_float4(0.f, 0.f, 0.f, 0.f);
    float4 a47 = make_float4(0.f, 0.f, 0.f, 0.f);

    #pragma unroll
    for (int c2 = 0; c2 < 2; ++c2) {
        int ch = half * 2 + c2;
        __syncthreads();   // first iter also covers W/sE loads
        #pragma unroll
        for (int i = 0; i < 8; ++i) {
            int l = lt + 128 * i;
            int nd = l >> 3, j = l & 7;
            int gn = base + nd;
            float4 v = (gn < n)
                ? reinterpret_cast<const float4*>(x)[gn * 32 + ch * 8 + j]
                : make_float4(0.f, 0.f, 0.f, 0.f);
            int sb = nd * 33 + j * 4;
            sx[half][sb + 0] = v.x; sx[half][sb + 1] = v.y;
            sx[half][sb + 2] = v.z; sx[half][sb + 3] = v.w;
        }
        __syncthreads();
        #pragma unroll
        for (int kk = 0; kk < 32; ++kk) {
            float xv = sx[half][lt * 33 + kk];
            int k = ch * 32 + kk;
            float4 wlo = sWlo[k], whi = sWhi[k];   // broadcast
            a03.x = fmaf(xv, wlo.x, a03.x); a03.y = fmaf(xv, wlo.y, a03.y);
            a03.z = fmaf(xv, wlo.z, a03.z); a03.w = fmaf(xv, wlo.w, a03.w);
            a47.x = fmaf(xv, whi.x, a47.x); a47.y = fmaf(xv, whi.y, a47.y);
            a47.z = fmaf(xv, whi.z, a47.z); a47.w = fmaf(xv, whi.w, a47.w);
        }
    }
    if (half == 1) {
        sPart[lt * 2 + 0] = a03;
        sPart[lt * 2 + 1] = a47;
    }
    __syncthreads();
    if (half == 0) {
        int node = base + lt;
        if (node < n) {
            float4 u0 = sPart[lt * 2 + 0], u1 = sPart[lt * 2 + 1];
            a03.x += u0.x; a03.y += u0.y; a03.z += u0.z; a03.w += u0.w;
            a47.x += u1.x; a47.y += u1.y; a47.z += u1.z; a47.w += u1.w;
            int d = dom[node] * 8;
            float dis = g_dis[node];
            a03.x = (a03.x + sE[d + 0]) * dis;
            a03.y = (a03.y + sE[d + 1]) * dis;
            a03.z = (a03.z + sE[d + 2]) * dis;
            a03.w = (a03.w + sE[d + 3]) * dis;
            a47.x = (a47.x + sE[d + 4]) * dis;
            a47.y = (a47.y + sE[d + 5]) * dis;
            a47.z = (a47.z + sE[d + 6]) * dis;
            a47.w = (a47.w + sE[d + 7]) * dis;
            float4* t1 = reinterpret_cast<float4*>(g_t1) + node * 2;
            t1[0] = a03;
            t1[1] = a47;
        }
    }
}

// ---------------------------------------------------------------------------
// Launch 4: scatter bare src index into per-dst buckets; 8 edges/thread.
__global__ void k_scatter(const int* __restrict__ src, const int* __restrict__ dst, int E) {
    int e = (blockIdx.x * blockDim.x + threadIdx.x) * 8;
    if (e + 8 <= E && (E & 7) == 0) {
        int4 da = *reinterpret_cast<const int4*>(dst + e);
        int4 db = *reinterpret_cast<const int4*>(dst + e + 4);
        int4 sa = *reinterpret_cast<const int4*>(src + e);
        int4 sb = *reinterpret_cast<const int4*>(src + e + 4);
        int p0 = atomicAdd(&g_cur[da.x], 1);
        int p1 = atomicAdd(&g_cur[da.y], 1);
        int p2 = atomicAdd(&g_cur[da.z], 1);
        int p3 = atomicAdd(&g_cur[da.w], 1);
        int p4 = atomicAdd(&g_cur[db.x], 1);
        int p5 = atomicAdd(&g_cur[db.y], 1);
        int p6 = atomicAdd(&g_cur[db.z], 1);
        int p7 = atomicAdd(&g_cur[db.w], 1);
        g_eSrc[p0] = sa.x; g_eSrc[p1] = sa.y;
        g_eSrc[p2] = sa.z; g_eSrc[p3] = sa.w;
        g_eSrc[p4] = sb.x; g_eSrc[p5] = sb.y;
        g_eSrc[p6] = sb.z; g_eSrc[p7] = sb.w;
    } else {
        int ee = min(e + 8, E);
        for (; e < ee; ++e) {
            int p = atomicAdd(&g_cur[dst[e]], 1);
            g_eSrc[p] = src[e];
        }
    }
}

// ---------------------------------------------------------------------------
// gather helper: plain sum of feat[src] over [off,end), 4 floats per thread
__device__ __forceinline__ float4 gather8(const float* __restrict__ feat,
                                          int off, int end, int q) {
    float4 a0 = make_float4(0.f, 0.f, 0.f, 0.f);
    float4 a1 = make_float4(0.f, 0.f, 0.f, 0.f);
    int e = off;
    for (; e + 4 <= end; e += 4) {
        int s0 = g_eSrc[e],     s1 = g_eSrc[e + 1];
        int s2 = g_eSrc[e + 2], s3 = g_eSrc[e + 3];
        float4 v0 = *reinterpret_cast<const float4*>(&feat[s0 * 8 + q * 4]);
        float4 v1 = *reinterpret_cast<const float4*>(&feat[s1 * 8 + q * 4]);
        float4 v2 = *reinterpret_cast<const float4*>(&feat[s2 * 8 + q * 4]);
        float4 v3 = *reinterpret_cast<const float4*>(&feat[s3 * 8 + q * 4]);
        a0.x += v0.x; a0.y += v0.y; a0.z += v0.z; a0.w += v0.w;
        a1.x += v1.x; a1.y += v1.y; a1.z += v1.z; a1.w += v1.w;
        a0.x += v2.x; a0.y += v2.y; a0.z += v2.z; a0.w += v2.w;
        a1.x += v3.x; a1.y += v3.y; a1.z += v3.z; a1.w += v3.w;
    }
    for (; e < end; ++e) {
        int s = g_eSrc[e];
        float4 v = *reinterpret_cast<const float4*>(&feat[s * 8 + q * 4]);
        a0.x += v.x; a0.y += v.y; a0.z += v.z; a0.w += v.w;
    }
    a0.x += a1.x; a0.y += a1.y; a0.z += a1.z; a0.w += a1.w;
    return a0;
}

// ---------------------------------------------------------------------------
// Launch 5: layer-1 gather + LoRA1-B + ReLU + W2 + A2 -> t2s (dis-scaled)
__global__ void __launch_bounds__(256) k_agg1mid(const float* __restrict__ B1,
                                                 const float* __restrict__ W2,
                                                 const float* __restrict__ A2, int n) {
    __shared__ float sB1[256], sW2[160], sA2[40], sC[8];
    int tid = threadIdx.x;
    if (tid < 256) sB1[tid] = B1[tid];
    if (tid < 160) sW2[tid] = W2[tid];
    if (tid < 40)  sA2[tid] = A2[tid];
    if (tid < 8)   sC[tid]  = g_cA1[tid];
    __syncthreads();

    int node = blockIdx.x * 128 + (tid >> 1);
    int q = tid & 1;
    float4 acc = make_float4(0.f, 0.f, 0.f, 0.f);
    float dis = 0.0f;
    if (node < n) {
        int off = g_off[node];
        int end = g_cur[node];
        acc = gather8(g_t1, off, end, q);
        dis = g_dis[node];
        float4 h = *reinterpret_cast<const float4*>(&g_t1[node * 8 + q * 4]);
        acc.x = fmaf(dis, acc.x + h.x, sC[q * 4 + 0]);
        acc.y = fmaf(dis, acc.y + h.y, sC[q * 4 + 1]);
        acc.z = fmaf(dis, acc.z + h.z, sC[q * 4 + 2]);
        acc.w = fmaf(dis, acc.w + h.w, sC[q * 4 + 3]);
    }
    float4 o;
    o.x = __shfl_xor_sync(0xFFFFFFFFu, acc.x, 1);
    o.y = __shfl_xor_sync(0xFFFFFFFFu, acc.y, 1);
    o.z = __shfl_xor_sync(0xFFFFFFFFu, acc.z, 1);
    o.w = __shfl_xor_sync(0xFFFFFFFFu, acc.w, 1);
    if (node < n && q == 0) {
        float a[8] = {acc.x, acc.y, acc.z, acc.w, o.x, o.y, o.z, o.w};
        float hw2[5] = {0, 0, 0, 0, 0};
        #pragma unroll
        for (int j = 0; j < 32; ++j) {
            float lv = 0.0f;
            #pragma unroll
            for (int r = 0; r < 8; ++r)
                lv = fmaf(a[r], sB1[r * 32 + j], lv);
            lv *= 0.125f;
            lv = fmaxf(lv, 0.0f);
            #pragma unroll
            for (int c = 0; c < 5; ++c)
                hw2[c] = fmaf(lv, sW2[j * 5 + c], hw2[c]);
        }
        float t2[8];
        #pragma unroll
        for (int r = 0; r < 8; ++r) {
            float s = 0.0f;
            #pragma unroll
            for (int c = 0; c < 5; ++c)
                s = fmaf(hw2[c], sA2[c * 8 + r], s);
            t2[r] = s * dis;
        }
        float4* p = reinterpret_cast<float4*>(g_t2) + node * 2;
        p[0] = make_float4(t2[0], t2[1], t2[2], t2[3]);
        p[1] = make_float4(t2[4], t2[5], t2[6], t2[7]);
    }
}

// ---------------------------------------------------------------------------
// Launch 6: layer-2 gather + LoRA2-B + log_softmax; resets g_deg
__global__ void __launch_bounds__(256) k_out(const float* __restrict__ B2,
                                             float* __restrict__ out, int n) {
    __shared__ float sB2[40], sC[8];
    int tid = threadIdx.x;
    if (tid < 40) sB2[tid] = B2[tid];
    if (tid < 8)  sC[tid]  = g_cA2[tid];
    __syncthreads();

    int node = blockIdx.x * 128 + (tid >> 1);
    int q = tid & 1;
    float4 acc = make_float4(0.f, 0.f, 0.f, 0.f);
    if (node < n) {
        int off = g_off[node];
        int end = g_cur[node];
        acc = gather8(g_t2, off, end, q);
        float dis = g_dis[node];
        float4 h = *reinterpret_cast<const float4*>(&g_t2[node * 8 + q * 4]);
        acc.x = fmaf(dis, acc.x + h.x, sC[q * 4 + 0]);
        acc.y = fmaf(dis, acc.y + h.y, sC[q * 4 + 1]);
        acc.z = fmaf(dis, acc.z + h.z, sC[q * 4 + 2]);
        acc.w = fmaf(dis, acc.w + h.w, sC[q * 4 + 3]);
        if (q == 0) g_deg[node] = 0;     // restore invariant for next call
    }
    float4 o;
    o.x = __shfl_xor_sync(0xFFFFFFFFu, acc.x, 1);
    o.y = __shfl_xor_sync(0xFFFFFFFFu, acc.y, 1);
    o.z = __shfl_xor_sync(0xFFFFFFFFu, acc.z, 1);
    o.w = __shfl_xor_sync(0xFFFFFFFFu, acc.w, 1);
    if (node < n && q == 0) {
        float a[8] = {acc.x, acc.y, acc.z, acc.w, o.x, o.y, o.z, o.w};
        float l[5];
        float m = -1e30f;
        #pragma unroll
        for (int c = 0; c < 5; ++c) {
            float s = 0.0f;
            #pragma unroll
            for (int r = 0; r < 8; ++r)
                s = fmaf(a[r], sB2[r * 5 + c], s);
            l[c] = s * 0.125f;
            m = fmaxf(m, l[c]);
        }
        float se = 0.0f;
        #pragma unroll
        for (int c = 0; c < 5; ++c) se += expf(l[c] - m);
        float lse = m + logf(se);
        #pragma unroll
        for (int c = 0; c < 5; ++c)
            out[node * 5 + c] = l[c] - lse;
    }
}

// ---------------------------------------------------------------------------
extern "C" void kernel_launch(void* const* d_in, const int* in_sizes, int n_in,
                              void* d_out, int out_size) {
    const float* x    = (const float*)d_in[0];
    const int*   ei   = (const int*)  d_in[1];
    const int*   dom  = (const int*)  d_in[2];
    const float* emb  = (const float*)d_in[3];
    const float* W1   = (const float*)d_in[4];
    const float* b1   = (const float*)d_in[5];
    const float* A1   = (const float*)d_in[6];
    const float* B1   = (const float*)d_in[7];
    const float* W2   = (const float*)d_in[8];
    const float* b2   = (const float*)d_in[9];
    const float* A2   = (const float*)d_in[10];
    const float* B2   = (const float*)d_in[11];
    float* out = (float*)d_out;

    int N = in_sizes[2];
    int E = in_sizes[1] / 2;
    const int* src = ei;
    const int* dst = ei + E;

    int nbScan = (N + SCAN_B - 1) / SCAN_B;
    int nbAgg  = (N + 127) / 128;
    int nbS2   = (N + 255) / 256;                 // scan2 blocks (256 nodes each)
    int nbT1   = (N + 127) / 128;                 // t1 blocks (128 nodes each)
    int ebVec  = (E + 8 * 256 - 1) / (8 * 256);   // 8 edges/thread

    k_pre        <<<32 + ebVec, 256>>>(dst, emb, W1, E);
    k_scan1_prep <<<nbScan + 1, SCAN_B>>>(W1, A1, b1, A2, b2, N);
    k_scan2_t1   <<<nbS2 + nbT1, 256>>>(x, dom, N, nbS2);
    k_scatter    <<<ebVec, 256>>>(src, dst, E);
    k_agg1mid    <<<nbAgg, 256>>>(B1, W2, A2, N);
    k_out        <<<nbAgg, 256>>>(B2, out, N);
}

// round 12
// speedup vs baseline: 1.0478x; 1.0478x over previous
#include <cuda_runtime.h>

// ---------------------------------------------------------------------------
// GCN_63694364999884 — rank-8 commuted aggregation; dis factored into source
// pre-scaling; bare-int CSR scatter (4-edge MLP); k-split smem-tiled t1
// merged with scan pass 2. 6 launches.
// ---------------------------------------------------------------------------

#define NMAX 50000
#define EMAX 1600000
#define SCAN_B 1024
#define NSCANB ((NMAX + SCAN_B - 1) / SCAN_B)   // 49

__device__ int   g_deg [NMAX];          // zeroed at end of k_out (self-restoring)
__device__ int   g_off [NMAX];
__device__ int   g_cur [NMAX];          // after scatter: end offsets
__device__ int   g_bsum[NSCANB];
__device__ float g_dis [NMAX];
__device__ float g_embW[3 * 32];        // zeroed at end of prep block
__device__ __align__(16) float g_W1A [128 * 8];
__device__ __align__(16) float g_embWA[3 * 8];
__device__ __align__(16) float g_cA1[8];
__device__ __align__(16) float g_cA2[8];
__device__ __align__(16) float g_t1[NMAX * 8];   // dis[i] * (x@W1A + embWA[dom])
__device__ __align__(16) float g_t2[NMAX * 8];   // dis[i] * (hW2 @ A2)
__device__ int   g_eSrc[EMAX];                   // src indices bucketed by dst

// ---------------------------------------------------------------------------
// Launch 1: blocks [0,32): embW = emb @ W1[:4096]; rest: degree count, 4 e/thr.
__global__ void k_pre(const int* __restrict__ dst,
                      const float* __restrict__ emb,
                      const float* __restrict__ W1, int E) {
    if (blockIdx.x < 32) {
        __shared__ float part[8][3][32];
        int col = threadIdx.x & 31;
        int w   = threadIdx.x >> 5;
        int k0  = blockIdx.x * 128 + w * 16;
        float a0 = 0.f, a1 = 0.f, a2 = 0.f;
        #pragma unroll 4
        for (int i = 0; i < 16; ++i) {
            int k = k0 + i;
            float wv = W1[k * 32 + col];
            a0 = fmaf(emb[k],        wv, a0);
            a1 = fmaf(emb[4096 + k], wv, a1);
            a2 = fmaf(emb[8192 + k], wv, a2);
        }
        part[w][0][col] = a0; part[w][1][col] = a1; part[w][2][col] = a2;
        __syncthreads();
        if (threadIdx.x < 96) {
            int d = threadIdx.x >> 5, c = threadIdx.x & 31;
            float s = 0.f;
            #pragma unroll
            for (int ww = 0; ww < 8; ++ww) s += part[ww][d][c];
            atomicAdd(&g_embW[d * 32 + c], s);
        }
    } else {
        int e = ((blockIdx.x - 32) * blockDim.x + threadIdx.x) * 4;
        if (e + 4 <= E) {
            if ((E & 3) == 0) {
                int4 d4 = *reinterpret_cast<const int4*>(dst + e);
                atomicAdd(&g_deg[d4.x], 1);
                atomicAdd(&g_deg[d4.y], 1);
                atomicAdd(&g_deg[d4.z], 1);
                atomicAdd(&g_deg[d4.w], 1);
            } else {
                atomicAdd(&g_deg[dst[e + 0]], 1);
                atomicAdd(&g_deg[dst[e + 1]], 1);
                atomicAdd(&g_deg[dst[e + 2]], 1);
                atomicAdd(&g_deg[dst[e + 3]], 1);
            }
        } else {
            for (; e < E; ++e) atomicAdd(&g_deg[dst[e]], 1);
        }
    }
}

// ---------------------------------------------------------------------------
// Launch 2: blocks [0,nbScan): per-block exclusive scan of deg + dis.
//           last block: prep (W1A, embWA, cA1, cA2) + embW reset.
__global__ void __launch_bounds__(SCAN_B) k_scan1_prep(
        const float* __restrict__ W1, const float* __restrict__ A1,
        const float* __restrict__ b1, const float* __restrict__ A2,
        const float* __restrict__ b2, int n) {
    if (blockIdx.x + 1 < gridDim.x) {
        __shared__ int wsum[32];
        int i = blockIdx.x * SCAN_B + threadIdx.x;
        int lane = threadIdx.x & 31, w = threadIdx.x >> 5;
        int v = (i < n) ? g_deg[i] : 0;
        if (i < n) g_dis[i] = rsqrtf((float)v + 1.0f);
        int s = v;
        #pragma unroll
        for (int o = 1; o < 32; o <<= 1) {
            int t = __shfl_up_sync(0xFFFFFFFFu, s, o);
            if (lane >= o) s += t;
        }
        if (lane == 31) wsum[w] = s;
        __syncthreads();
        if (w == 0) {
            int ws = wsum[lane];
            #pragma unroll
            for (int o = 1; o < 32; o <<= 1) {
                int t = __shfl_up_sync(0xFFFFFFFFu, ws, o);
                if (lane >= o) ws += t;
            }
            wsum[lane] = ws;
        }
        __syncthreads();
        int pre = (w > 0) ? wsum[w - 1] : 0;
        int incl = s + pre;
        if (i < n) g_off[i] = incl - v;
        if (threadIdx.x == SCAN_B - 1) g_bsum[blockIdx.x] = incl;
    } else {
        __shared__ float sA1[256];
        int tid = threadIdx.x;
        if (tid < 256) sA1[tid] = A1[tid];
        __syncthreads();
        {   // W1A[k][r], 1024 threads
            int k = tid >> 3, r = tid & 7;
            float acc = 0.f;
            #pragma unroll
            for (int j = 0; j < 32; ++j)
                acc = fmaf(W1[(4096 + k) * 32 + j], sA1[j * 8 + r], acc);
            g_W1A[tid] = acc;
        }
        if (tid < 24) {
            int d = tid >> 3, r = tid & 7;
            float acc = 0.f;
            #pragma unroll
            for (int j = 0; j < 32; ++j)
                acc = fmaf(g_embW[d * 32 + j], sA1[j * 8 + r], acc);
            g_embWA[tid] = acc;
        } else if (tid < 32) {
            int r = tid - 24;
            float acc = 0.f;
            #pragma unroll
            for (int j = 0; j < 32; ++j)
                acc = fmaf(b1[j], sA1[j * 8 + r], acc);
            g_cA1[r] = acc;
        } else if (tid < 40) {
            int r = tid - 32;
            float acc = 0.f;
            #pragma unroll
            for (int c = 0; c < 5; ++c)
                acc = fmaf(b2[c], A2[c * 8 + r], acc);
            g_cA2[r] = acc;
        }
        __syncthreads();
        if (tid < 96) g_embW[tid] = 0.0f;   // restore for next call
    }
}

// ---------------------------------------------------------------------------
// Launch 3 (merged): blocks [0,nbS2): scan pass 2 (256 nodes/block, block
// prefix re-derived from g_bsum). blocks [nbS2,..): t1 GEMM, k-split
// across two 128-thread halves over 128 nodes.
__global__ void __launch_bounds__(256) k_scan2_t1(
        const float* __restrict__ x, const int* __restrict__ dom,
        int n, int nbS2) {
    int tid = threadIdx.x;
    if ((int)blockIdx.x < nbS2) {
        __shared__ int sred[2];
        int top = blockIdx.x >> 2;            // bsum entries fully before this block
        if (tid < 64) {
            int v = (tid < top) ? g_bsum[tid] : 0;   // top <= 48 < 64
            #pragma unroll
            for (int o = 16; o > 0; o >>= 1)
                v += __shfl_down_sync(0xFFFFFFFFu, v, o);
            if ((tid & 31) == 0) sred[tid >> 5] = v;
        }
        __syncthreads();
        int bpre = sred[0] + sred[1];
        int i = blockIdx.x * 256 + tid;
        if (i < n) {
            int o = g_off[i] + bpre;
            g_off[i] = o;
            g_cur[i] = o;
        }
        return;
    }
    // ---- t1 part ----
    __shared__ float  sx[2][128 * 33];       // 33.8 KB (one buffer per k-half)
    __shared__ float4 sWlo[128], sWhi[128];  // 4 KB
    __shared__ float  sE[24];
    __shared__ float4 sPart[256];            // upper-half partials, 4 KB

    int half = tid >> 7;          // 0: k 0-63,  1: k 64-127
    int lt   = tid & 127;
    if (tid < 128) {
        const float4* W4 = reinterpret_cast<const float4*>(g_W1A);
        sWlo[tid] = W4[tid * 2];
        sWhi[tid] = W4[tid * 2 + 1];
    }
    if (tid < 24) sE[tid] = g_embWA[tid];

    int base = (blockIdx.x - nbS2) * 128;
    float4 a03 = make_float4(0.f, 0.f, 0.f, 0.f);
    float4 a47 = make_float4(0.f, 0.f, 0.f, 0.f);

    #pragma unroll
    for (int c2 = 0; c2 < 2; ++c2) {
        int ch = half * 2 + c2;
        __syncthreads();   // first iter also covers W/sE loads
        #pragma unroll
        for (int i = 0; i < 8; ++i) {
            int l = lt + 128 * i;
            int nd = l >> 3, j = l & 7;
            int gn = base + nd;
            float4 v = (gn < n)
                ? reinterpret_cast<const float4*>(x)[gn * 32 + ch * 8 + j]
                : make_float4(0.f, 0.f, 0.f, 0.f);
            int sb = nd * 33 + j * 4;
            sx[half][sb + 0] = v.x; sx[half][sb + 1] = v.y;
            sx[half][sb + 2] = v.z; sx[half][sb + 3] = v.w;
        }
        __syncthreads();
        #pragma unroll
        for (int kk = 0; kk < 32; ++kk) {
            float xv = sx[half][lt * 33 + kk];
            int k = ch * 32 + kk;
            float4 wlo = sWlo[k], whi = sWhi[k];   // broadcast
            a03.x = fmaf(xv, wlo.x, a03.x); a03.y = fmaf(xv, wlo.y, a03.y);
            a03.z = fmaf(xv, wlo.z, a03.z); a03.w = fmaf(xv, wlo.w, a03.w);
            a47.x = fmaf(xv, whi.x, a47.x); a47.y = fmaf(xv, whi.y, a47.y);
            a47.z = fmaf(xv, whi.z, a47.z); a47.w = fmaf(xv, whi.w, a47.w);
        }
    }
    if (half == 1) {
        sPart[lt * 2 + 0] = a03;
        sPart[lt * 2 + 1] = a47;
    }
    __syncthreads();
    if (half == 0) {
        int node = base + lt;
        if (node < n) {
            float4 u0 = sPart[lt * 2 + 0], u1 = sPart[lt * 2 + 1];
            a03.x += u0.x; a03.y += u0.y; a03.z += u0.z; a03.w += u0.w;
            a47.x += u1.x; a47.y += u1.y; a47.z += u1.z; a47.w += u1.w;
            int d = dom[node] * 8;
            float dis = g_dis[node];
            a03.x = (a03.x + sE[d + 0]) * dis;
            a03.y = (a03.y + sE[d + 1]) * dis;
            a03.z = (a03.z + sE[d + 2]) * dis;
            a03.w = (a03.w + sE[d + 3]) * dis;
            a47.x = (a47.x + sE[d + 4]) * dis;
            a47.y = (a47.y + sE[d + 5]) * dis;
            a47.z = (a47.z + sE[d + 6]) * dis;
            a47.w = (a47.w + sE[d + 7]) * dis;
            float4* t1 = reinterpret_cast<float4*>(g_t1) + node * 2;
            t1[0] = a03;
            t1[1] = a47;
        }
    }
}

// ---------------------------------------------------------------------------
// Launch 4: scatter bare src index into per-dst buckets; 4 edges/thread.
__global__ void k_scatter(const int* __restrict__ src, const int* __restrict__ dst, int E) {
    int e = (blockIdx.x * blockDim.x + threadIdx.x) * 4;
    if (e + 4 <= E) {
        int d0, d1, d2, d3, s0, s1, s2, s3;
        if ((E & 3) == 0) {
            int4 d4 = *reinterpret_cast<const int4*>(dst + e);
            int4 s4 = *reinterpret_cast<const int4*>(src + e);
            d0 = d4.x; d1 = d4.y; d2 = d4.z; d3 = d4.w;
            s0 = s4.x; s1 = s4.y; s2 = s4.z; s3 = s4.w;
        } else {
            d0 = dst[e]; d1 = dst[e + 1]; d2 = dst[e + 2]; d3 = dst[e + 3];
            s0 = src[e]; s1 = src[e + 1]; s2 = src[e + 2]; s3 = src[e + 3];
        }
        int p0 = atomicAdd(&g_cur[d0], 1);
        int p1 = atomicAdd(&g_cur[d1], 1);
        int p2 = atomicAdd(&g_cur[d2], 1);
        int p3 = atomicAdd(&g_cur[d3], 1);
        g_eSrc[p0] = s0;
        g_eSrc[p1] = s1;
        g_eSrc[p2] = s2;
        g_eSrc[p3] = s3;
    } else {
        for (; e < E; ++e) {
            int p = atomicAdd(&g_cur[dst[e]], 1);
            g_eSrc[p] = src[e];
        }
    }
}

// ---------------------------------------------------------------------------
// gather helper: plain sum of feat[src] over [off,end), 4 floats per thread
__device__ __forceinline__ float4 gather8(const float* __restrict__ feat,
                                          int off, int end, int q) {
    float4 a0 = make_float4(0.f, 0.f, 0.f, 0.f);
    float4 a1 = make_float4(0.f, 0.f, 0.f, 0.f);
    int e = off;
    for (; e + 4 <= end; e += 4) {
        int s0 = g_eSrc[e],     s1 = g_eSrc[e + 1];
        int s2 = g_eSrc[e + 2], s3 = g_eSrc[e + 3];
        float4 v0 = *reinterpret_cast<const float4*>(&feat[s0 * 8 + q * 4]);
        float4 v1 = *reinterpret_cast<const float4*>(&feat[s1 * 8 + q * 4]);
        float4 v2 = *reinterpret_cast<const float4*>(&feat[s2 * 8 + q * 4]);
        float4 v3 = *reinterpret_cast<const float4*>(&feat[s3 * 8 + q * 4]);
        a0.x += v0.x; a0.y += v0.y; a0.z += v0.z; a0.w += v0.w;
        a1.x += v1.x; a1.y += v1.y; a1.z += v1.z; a1.w += v1.w;
        a0.x += v2.x; a0.y += v2.y; a0.z += v2.z; a0.w += v2.w;
        a1.x += v3.x; a1.y += v3.y; a1.z += v3.z; a1.w += v3.w;
    }
    for (; e < end; ++e) {
        int s = g_eSrc[e];
        float4 v = *reinterpret_cast<const float4*>(&feat[s * 8 + q * 4]);
        a0.x += v.x; a0.y += v.y; a0.z += v.z; a0.w += v.w;
    }
    a0.x += a1.x; a0.y += a1.y; a0.z += a1.z; a0.w += a1.w;
    return a0;
}

// ---------------------------------------------------------------------------
// Launch 5: layer-1 gather + LoRA1-B + ReLU + W2 + A2 -> t2s (dis-scaled)
__global__ void __launch_bounds__(256) k_agg1mid(const float* __restrict__ B1,
                                                 const float* __restrict__ W2,
                                                 const float* __restrict__ A2, int n) {
    __shared__ float sB1[256], sW2[160], sA2[40], sC[8];
    int tid = threadIdx.x;
    if (tid < 256) sB1[tid] = B1[tid];
    if (tid < 160) sW2[tid] = W2[tid];
    if (tid < 40)  sA2[tid] = A2[tid];
    if (tid < 8)   sC[tid]  = g_cA1[tid];
    __syncthreads();

    int node = blockIdx.x * 128 + (tid >> 1);
    int q = tid & 1;
    float4 acc = make_float4(0.f, 0.f, 0.f, 0.f);
    float dis = 0.0f;
    if (node < n) {
        int off = g_off[node];
        int end = g_cur[node];
        acc = gather8(g_t1, off, end, q);
        dis = g_dis[node];
        float4 h = *reinterpret_cast<const float4*>(&g_t1[node * 8 + q * 4]);
        acc.x = fmaf(dis, acc.x + h.x, sC[q * 4 + 0]);
        acc.y = fmaf(dis, acc.y + h.y, sC[q * 4 + 1]);
        acc.z = fmaf(dis, acc.z + h.z, sC[q * 4 + 2]);
        acc.w = fmaf(dis, acc.w + h.w, sC[q * 4 + 3]);
    }
    float4 o;
    o.x = __shfl_xor_sync(0xFFFFFFFFu, acc.x, 1);
    o.y = __shfl_xor_sync(0xFFFFFFFFu, acc.y, 1);
    o.z = __shfl_xor_sync(0xFFFFFFFFu, acc.z, 1);
    o.w = __shfl_xor_sync(0xFFFFFFFFu, acc.w, 1);
    if (node < n && q == 0) {
        float a[8] = {acc.x, acc.y, acc.z, acc.w, o.x, o.y, o.z, o.w};
        float hw2[5] = {0, 0, 0, 0, 0};
        #pragma unroll
        for (int j = 0; j < 32; ++j) {
            float lv = 0.0f;
            #pragma unroll
            for (int r = 0; r < 8; ++r)
                lv = fmaf(a[r], sB1[r * 32 + j], lv);
            lv *= 0.125f;
            lv = fmaxf(lv, 0.0f);
            #pragma unroll
            for (int c = 0; c < 5; ++c)
                hw2[c] = fmaf(lv, sW2[j * 5 + c], hw2[c]);
        }
        float t2[8];
        #pragma unroll
        for (int r = 0; r < 8; ++r) {
            float s = 0.0f;
            #pragma unroll
            for (int c = 0; c < 5; ++c)
                s = fmaf(hw2[c], sA2[c * 8 + r], s);
            t2[r] = s * dis;
        }
        float4* p = reinterpret_cast<float4*>(g_t2) + node * 2;
        p[0] = make_float4(t2[0], t2[1], t2[2], t2[3]);
        p[1] = make_float4(t2[4], t2[5], t2[6], t2[7]);
    }
}

// ---------------------------------------------------------------------------
// Launch 6: layer-2 gather + LoRA2-B + log_softmax; resets g_deg
__global__ void __launch_bounds__(256) k_out(const float* __restrict__ B2,
                                             float* __restrict__ out, int n) {
    __shared__ float sB2[40], sC[8];
    int tid = threadIdx.x;
    if (tid < 40) sB2[tid] = B2[tid];
    if (tid < 8)  sC[tid]  = g_cA2[tid];
    __syncthreads();

    int node = blockIdx.x * 128 + (tid >> 1);
    int q = tid & 1;
    float4 acc = make_float4(0.f, 0.f, 0.f, 0.f);
    if (node < n) {
        int off = g_off[node];
        int end = g_cur[node];
        acc = gather8(g_t2, off, end, q);
        float dis = g_dis[node];
        float4 h = *reinterpret_cast<const float4*>(&g_t2[node * 8 + q * 4]);
        acc.x = fmaf(dis, acc.x + h.x, sC[q * 4 + 0]);
        acc.y = fmaf(dis, acc.y + h.y, sC[q * 4 + 1]);
        acc.z = fmaf(dis, acc.z + h.z, sC[q * 4 + 2]);
        acc.w = fmaf(dis, acc.w + h.w, sC[q * 4 + 3]);
        if (q == 0) g_deg[node] = 0;     // restore invariant for next call
    }
    float4 o;
    o.x = __shfl_xor_sync(0xFFFFFFFFu, acc.x, 1);
    o.y = __shfl_xor_sync(0xFFFFFFFFu, acc.y, 1);
    o.z = __shfl_xor_sync(0xFFFFFFFFu, acc.z, 1);
    o.w = __shfl_xor_sync(0xFFFFFFFFu, acc.w, 1);
    if (node < n && q == 0) {
        float a[8] = {acc.x, acc.y, acc.z, acc.w, o.x, o.y, o.z, o.w};
        float l[5];
        float m = -1e30f;
        #pragma unroll
        for (int c = 0; c < 5; ++c) {
            float s = 0.0f;
            #pragma unroll
            for (int r = 0; r < 8; ++r)
                s = fmaf(a[r], sB2[r * 5 + c], s);
            l[c] = s * 0.125f;
            m = fmaxf(m, l[c]);
        }
        float se = 0.0f;
        #pragma unroll
        for (int c = 0; c < 5; ++c) se += expf(l[c] - m);
        float lse = m + logf(se);
        #pragma unroll
        for (int c = 0; c < 5; ++c)
            out[node * 5 + c] = l[c] - lse;
    }
}

// ---------------------------------------------------------------------------
extern "C" void kernel_launch(void* const* d_in, const int* in_sizes, int n_in,
                              void* d_out, int out_size) {
    const float* x    = (const float*)d_in[0];
    const int*   ei   = (const int*)  d_in[1];
    const int*   dom  = (const int*)  d_in[2];
    const float* emb  = (const float*)d_in[3];
    const float* W1   = (const float*)d_in[4];
    const float* b1   = (const float*)d_in[5];
    const float* A1   = (const float*)d_in[6];
    const float* B1   = (const float*)d_in[7];
    const float* W2   = (const float*)d_in[8];
    const float* b2   = (const float*)d_in[9];
    const float* A2   = (const float*)d_in[10];
    const float* B2   = (const float*)d_in[11];
    float* out = (float*)d_out;

    int N = in_sizes[2];
    int E = in_sizes[1] / 2;
    const int* src = ei;
    const int* dst = ei + E;

    int nbScan = (N + SCAN_B - 1) / SCAN_B;
    int nbAgg  = (N + 127) / 128;
    int nbS2   = (N + 255) / 256;                 // scan2 blocks (256 nodes each)
    int nbT1   = (N + 127) / 128;                 // t1 blocks (128 nodes each)
    int ebVec  = (E + 4 * 256 - 1) / (4 * 256);   // 4 edges/thread

    k_pre        <<<32 + ebVec, 256>>>(dst, emb, W1, E);
    k_scan1_prep <<<nbScan + 1, SCAN_B>>>(W1, A1, b1, A2, b2, N);
    k_scan2_t1   <<<nbS2 + nbT1, 256>>>(x, dom, N, nbS2);
    k_scatter    <<<ebVec, 256>>>(src, dst, E);
    k_agg1mid    <<<nbAgg, 256>>>(B1, W2, A2, N);
    k_out        <<<nbAgg, 256>>>(B2, out, N);
}

// round 13
// speedup vs baseline: 1.0751x; 1.0260x over previous
#include <cuda_runtime.h>

// ---------------------------------------------------------------------------
// GCN_63694364999884 — rank-8 commuted aggregation; dis factored into source
// pre-scaling; atomic-free CSR scatter (ranks captured during degree count);
// k-split smem-tiled t1 merged with scan pass 2. 6 launches.
// ---------------------------------------------------------------------------

#define NMAX 50000
#define EMAX 1600000
#define SCAN_B 1024
#define NSCANB ((NMAX + SCAN_B - 1) / SCAN_B)   // 49

__device__ int   g_deg [NMAX];          // zeroed at end of k_out (self-restoring)
__device__ int   g_off [NMAX];
__device__ int   g_cur [NMAX];          // end offsets (off + deg)
__device__ int   g_bsum[NSCANB];
__device__ float g_dis [NMAX];
__device__ float g_embW[3 * 32];        // zeroed at end of prep block
__device__ __align__(16) float g_W1A [128 * 8];
__device__ __align__(16) float g_embWA[3 * 8];
__device__ __align__(16) float g_cA1[8];
__device__ __align__(16) float g_cA2[8];
__device__ __align__(16) float g_t1[NMAX * 8];   // dis[i] * (x@W1A + embWA[dom])
__device__ __align__(16) float g_t2[NMAX * 8];   // dis[i] * (hW2 @ A2)
__device__ int   g_eSrc[EMAX];                   // src indices bucketed by dst
__device__ int   g_rank[EMAX];                   // per-edge rank within dst bucket

// ---------------------------------------------------------------------------
// Launch 1: blocks [0,32): embW = emb @ W1[:4096];
//           rest: degree count capturing per-edge bucket ranks, 4 e/thr.
__global__ void k_pre(const int* __restrict__ dst,
                      const float* __restrict__ emb,
                      const float* __restrict__ W1, int E) {
    if (blockIdx.x < 32) {
        __shared__ float part[8][3][32];
        int col = threadIdx.x & 31;
        int w   = threadIdx.x >> 5;
        int k0  = blockIdx.x * 128 + w * 16;
        float a0 = 0.f, a1 = 0.f, a2 = 0.f;
        #pragma unroll 4
        for (int i = 0; i < 16; ++i) {
            int k = k0 + i;
            float wv = W1[k * 32 + col];
            a0 = fmaf(emb[k],        wv, a0);
            a1 = fmaf(emb[4096 + k], wv, a1);
            a2 = fmaf(emb[8192 + k], wv, a2);
        }
        part[w][0][col] = a0; part[w][1][col] = a1; part[w][2][col] = a2;
        __syncthreads();
        if (threadIdx.x < 96) {
            int d = threadIdx.x >> 5, c = threadIdx.x & 31;
            float s = 0.f;
            #pragma unroll
            for (int ww = 0; ww < 8; ++ww) s += part[ww][d][c];
            atomicAdd(&g_embW[d * 32 + c], s);
        }
    } else {
        int e = ((blockIdx.x - 32) * blockDim.x + threadIdx.x) * 4;
        if (e + 4 <= E && (E & 3) == 0) {
            int4 d4 = *reinterpret_cast<const int4*>(dst + e);
            int4 r4;
            r4.x = atomicAdd(&g_deg[d4.x], 1);
            r4.y = atomicAdd(&g_deg[d4.y], 1);
            r4.z = atomicAdd(&g_deg[d4.z], 1);
            r4.w = atomicAdd(&g_deg[d4.w], 1);
            *reinterpret_cast<int4*>(g_rank + e) = r4;   // coalesced
        } else {
            int ee = min(e + 4, E);
            for (; e < ee; ++e)
                g_rank[e] = atomicAdd(&g_deg[dst[e]], 1);
        }
    }
}

// ---------------------------------------------------------------------------
// Launch 2: blocks [0,nbScan): per-block exclusive scan of deg + dis.
//           last block: prep (W1A, embWA, cA1, cA2) + embW reset.
__global__ void __launch_bounds__(SCAN_B) k_scan1_prep(
        const float* __restrict__ W1, const float* __restrict__ A1,
        const float* __restrict__ b1, const float* __restrict__ A2,
        const float* __restrict__ b2, int n) {
    if (blockIdx.x + 1 < gridDim.x) {
        __shared__ int wsum[32];
        int i = blockIdx.x * SCAN_B + threadIdx.x;
        int lane = threadIdx.x & 31, w = threadIdx.x >> 5;
        int v = (i < n) ? g_deg[i] : 0;
        if (i < n) g_dis[i] = rsqrtf((float)v + 1.0f);
        int s = v;
        #pragma unroll
        for (int o = 1; o < 32; o <<= 1) {
            int t = __shfl_up_sync(0xFFFFFFFFu, s, o);
            if (lane >= o) s += t;
        }
        if (lane == 31) wsum[w] = s;
        __syncthreads();
        if (w == 0) {
            int ws = wsum[lane];
            #pragma unroll
            for (int o = 1; o < 32; o <<= 1) {
                int t = __shfl_up_sync(0xFFFFFFFFu, ws, o);
                if (lane >= o) ws += t;
            }
            wsum[lane] = ws;
        }
        __syncthreads();
        int pre = (w > 0) ? wsum[w - 1] : 0;
        int incl = s + pre;
        if (i < n) g_off[i] = incl - v;
        if (threadIdx.x == SCAN_B - 1) g_bsum[blockIdx.x] = incl;
    } else {
        __shared__ float sA1[256];
        int tid = threadIdx.x;
        if (tid < 256) sA1[tid] = A1[tid];
        __syncthreads();
        {   // W1A[k][r], 1024 threads
            int k = tid >> 3, r = tid & 7;
            float acc = 0.f;
            #pragma unroll
            for (int j = 0; j < 32; ++j)
                acc = fmaf(W1[(4096 + k) * 32 + j], sA1[j * 8 + r], acc);
            g_W1A[tid] = acc;
        }
        if (tid < 24) {
            int d = tid >> 3, r = tid & 7;
            float acc = 0.f;
            #pragma unroll
            for (int j = 0; j < 32; ++j)
                acc = fmaf(g_embW[d * 32 + j], sA1[j * 8 + r], acc);
            g_embWA[tid] = acc;
        } else if (tid < 32) {
            int r = tid - 24;
            float acc = 0.f;
            #pragma unroll
            for (int j = 0; j < 32; ++j)
                acc = fmaf(b1[j], sA1[j * 8 + r], acc);
            g_cA1[r] = acc;
        } else if (tid < 40) {
            int r = tid - 32;
            float acc = 0.f;
            #pragma unroll
            for (int c = 0; c < 5; ++c)
                acc = fmaf(b2[c], A2[c * 8 + r], acc);
            g_cA2[r] = acc;
        }
        __syncthreads();
        if (tid < 96) g_embW[tid] = 0.0f;   // restore for next call
    }
}

// ---------------------------------------------------------------------------
// Launch 3 (merged): blocks [0,nbS2): scan pass 2 (256 nodes/block, block
// prefix re-derived from g_bsum); also writes end offsets (g_cur).
// blocks [nbS2,..): t1 GEMM, k-split across two 128-thread halves.
__global__ void __launch_bounds__(256) k_scan2_t1(
        const float* __restrict__ x, const int* __restrict__ dom,
        int n, int nbS2) {
    int tid = threadIdx.x;
    if ((int)blockIdx.x < nbS2) {
        __shared__ int sred[2];
        int top = blockIdx.x >> 2;            // bsum entries fully before this block
        if (tid < 64) {
            int v = (tid < top) ? g_bsum[tid] : 0;   // top <= 48 < 64
            #pragma unroll
            for (int o = 16; o > 0; o >>= 1)
                v += __shfl_down_sync(0xFFFFFFFFu, v, o);
            if ((tid & 31) == 0) sred[tid >> 5] = v;
        }
        __syncthreads();
        int bpre = sred[0] + sred[1];
        int i = blockIdx.x * 256 + tid;
        if (i < n) {
            int o = g_off[i] + bpre;
            g_off[i] = o;
            g_cur[i] = o + g_deg[i];      // end offset
        }
        return;
    }
    // ---- t1 part ----
    __shared__ float  sx[2][128 * 33];       // 33.8 KB (one buffer per k-half)
    __shared__ float4 sWlo[128], sWhi[128];  // 4 KB
    __shared__ float  sE[24];
    __shared__ float4 sPart[256];            // upper-half partials, 4 KB

    int half = tid >> 7;          // 0: k 0-63,  1: k 64-127
    int lt   = tid & 127;
    if (tid < 128) {
        const float4* W4 = reinterpret_cast<const float4*>(g_W1A);
        sWlo[tid] = W4[tid * 2];
        sWhi[tid] = W4[tid * 2 + 1];
    }
    if (tid < 24) sE[tid] = g_embWA[tid];

    int base = (blockIdx.x - nbS2) * 128;
    float4 a03 = make_float4(0.f, 0.f, 0.f, 0.f);
    float4 a47 = make_float4(0.f, 0.f, 0.f, 0.f);

    #pragma unroll
    for (int c2 = 0; c2 < 2; ++c2) {
        int ch = half * 2 + c2;
        __syncthreads();   // first iter also covers W/sE loads
        #pragma unroll
        for (int i = 0; i < 8; ++i) {
            int l = lt + 128 * i;
            int nd = l >> 3, j = l & 7;
            int gn = base + nd;
            float4 v = (gn < n)
                ? reinterpret_cast<const float4*>(x)[gn * 32 + ch * 8 + j]
                : make_float4(0.f, 0.f, 0.f, 0.f);
            int sb = nd * 33 + j * 4;
            sx[half][sb + 0] = v.x; sx[half][sb + 1] = v.y;
            sx[half][sb + 2] = v.z; sx[half][sb + 3] = v.w;
        }
        __syncthreads();
        #pragma unroll
        for (int kk = 0; kk < 32; ++kk) {
            float xv = sx[half][lt * 33 + kk];
            int k = ch * 32 + kk;
            float4 wlo = sWlo[k], whi = sWhi[k];   // broadcast
            a03.x = fmaf(xv, wlo.x, a03.x); a03.y = fmaf(xv, wlo.y, a03.y);
            a03.z = fmaf(xv, wlo.z, a03.z); a03.w = fmaf(xv, wlo.w, a03.w);
            a47.x = fmaf(xv, whi.x, a47.x); a47.y = fmaf(xv, whi.y, a47.y);
            a47.z = fmaf(xv, whi.z, a47.z); a47.w = fmaf(xv, whi.w, a47.w);
        }
    }
    if (half == 1) {
        sPart[lt * 2 + 0] = a03;
        sPart[lt * 2 + 1] = a47;
    }
    __syncthreads();
    if (half == 0) {
        int node = base + lt;
        if (node < n) {
            float4 u0 = sPart[lt * 2 + 0], u1 = sPart[lt * 2 + 1];
            a03.x += u0.x; a03.y += u0.y; a03.z += u0.z; a03.w += u0.w;
            a47.x += u1.x; a47.y += u1.y; a47.z += u1.z; a47.w += u1.w;
            int d = dom[node] * 8;
            float dis = g_dis[node];
            a03.x = (a03.x + sE[d + 0]) * dis;
            a03.y = (a03.y + sE[d + 1]) * dis;
            a03.z = (a03.z + sE[d + 2]) * dis;
            a03.w = (a03.w + sE[d + 3]) * dis;
            a47.x = (a47.x + sE[d + 4]) * dis;
            a47.y = (a47.y + sE[d + 5]) * dis;
            a47.z = (a47.z + sE[d + 6]) * dis;
            a47.w = (a47.w + sE[d + 7]) * dis;
            float4* t1 = reinterpret_cast<float4*>(g_t1) + node * 2;
            t1[0] = a03;
            t1[1] = a47;
        }
    }
}

// ---------------------------------------------------------------------------
// Launch 4: atomic-free scatter: g_eSrc[off[dst] + rank] = src. 4 e/thr.
__global__ void k_scatter(const int* __restrict__ src, const int* __restrict__ dst, int E) {
    int e = (blockIdx.x * blockDim.x + threadIdx.x) * 4;
    if (e + 4 <= E && (E & 3) == 0) {
        int4 d4 = *reinterpret_cast<const int4*>(dst + e);
        int4 r4 = *reinterpret_cast<const int4*>(g_rank + e);
        int4 s4 = *reinterpret_cast<const int4*>(src + e);
        int o0 = g_off[d4.x];
        int o1 = g_off[d4.y];
        int o2 = g_off[d4.z];
        int o3 = g_off[d4.w];
        g_eSrc[o0 + r4.x] = s4.x;
        g_eSrc[o1 + r4.y] = s4.y;
        g_eSrc[o2 + r4.z] = s4.z;
        g_eSrc[o3 + r4.w] = s4.w;
    } else {
        int ee = min(e + 4, E);
        for (; e < ee; ++e)
            g_eSrc[g_off[dst[e]] + g_rank[e]] = src[e];
    }
}

// ---------------------------------------------------------------------------
// gather helper: plain sum of feat[src] over [off,end), 4 floats per thread
__device__ __forceinline__ float4 gather8(const float* __restrict__ feat,
                                          int off, int end, int q) {
    float4 a0 = make_float4(0.f, 0.f, 0.f, 0.f);
    float4 a1 = make_float4(0.f, 0.f, 0.f, 0.f);
    int e = off;
    for (; e + 4 <= end; e += 4) {
        int s0 = g_eSrc[e],     s1 = g_eSrc[e + 1];
        int s2 = g_eSrc[e + 2], s3 = g_eSrc[e + 3];
        float4 v0 = *reinterpret_cast<const float4*>(&feat[s0 * 8 + q * 4]);
        float4 v1 = *reinterpret_cast<const float4*>(&feat[s1 * 8 + q * 4]);
        float4 v2 = *reinterpret_cast<const float4*>(&feat[s2 * 8 + q * 4]);
        float4 v3 = *reinterpret_cast<const float4*>(&feat[s3 * 8 + q * 4]);
        a0.x += v0.x; a0.y += v0.y; a0.z += v0.z; a0.w += v0.w;
        a1.x += v1.x; a1.y += v1.y; a1.z += v1.z; a1.w += v1.w;
        a0.x += v2.x; a0.y += v2.y; a0.z += v2.z; a0.w += v2.w;
        a1.x += v3.x; a1.y += v3.y; a1.z += v3.z; a1.w += v3.w;
    }
    for (; e < end; ++e) {
        int s = g_eSrc[e];
        float4 v = *reinterpret_cast<const float4*>(&feat[s * 8 + q * 4]);
        a0.x += v.x; a0.y += v.y; a0.z += v.z; a0.w += v.w;
    }
    a0.x += a1.x; a0.y += a1.y; a0.z += a1.z; a0.w += a1.w;
    return a0;
}

// ---------------------------------------------------------------------------
// Launch 5: layer-1 gather + LoRA1-B + ReLU + W2 + A2 -> t2s (dis-scaled)
__global__ void __launch_bounds__(256) k_agg1mid(const float* __restrict__ B1,
                                                 const float* __restrict__ W2,
                                                 const float* __restrict__ A2, int n) {
    __shared__ float sB1[256], sW2[160], sA2[40], sC[8];
    int tid = threadIdx.x;
    if (tid < 256) sB1[tid] = B1[tid];
    if (tid < 160) sW2[tid] = W2[tid];
    if (tid < 40)  sA2[tid] = A2[tid];
    if (tid < 8)   sC[tid]  = g_cA1[tid];
    __syncthreads();

    int node = blockIdx.x * 128 + (tid >> 1);
    int q = tid & 1;
    float4 acc = make_float4(0.f, 0.f, 0.f, 0.f);
    float dis = 0.0f;
    if (node < n) {
        int off = g_off[node];
        int end = g_cur[node];
        acc = gather8(g_t1, off, end, q);
        dis = g_dis[node];
        float4 h = *reinterpret_cast<const float4*>(&g_t1[node * 8 + q * 4]);
        acc.x = fmaf(dis, acc.x + h.x, sC[q * 4 + 0]);
        acc.y = fmaf(dis, acc.y + h.y, sC[q * 4 + 1]);
        acc.z = fmaf(dis, acc.z + h.z, sC[q * 4 + 2]);
        acc.w = fmaf(dis, acc.w + h.w, sC[q * 4 + 3]);
    }
    float4 o;
    o.x = __shfl_xor_sync(0xFFFFFFFFu, acc.x, 1);
    o.y = __shfl_xor_sync(0xFFFFFFFFu, acc.y, 1);
    o.z = __shfl_xor_sync(0xFFFFFFFFu, acc.z, 1);
    o.w = __shfl_xor_sync(0xFFFFFFFFu, acc.w, 1);
    if (node < n && q == 0) {
        float a[8] = {acc.x, acc.y, acc.z, acc.w, o.x, o.y, o.z, o.w};
        float hw2[5] = {0, 0, 0, 0, 0};
        #pragma unroll
        for (int j = 0; j < 32; ++j) {
            float lv = 0.0f;
            #pragma unroll
            for (int r = 0; r < 8; ++r)
                lv = fmaf(a[r], sB1[r * 32 + j], lv);
            lv *= 0.125f;
            lv = fmaxf(lv, 0.0f);
            #pragma unroll
            for (int c = 0; c < 5; ++c)
                hw2[c] = fmaf(lv, sW2[j * 5 + c], hw2[c]);
        }
        float t2[8];
        #pragma unroll
        for (int r = 0; r < 8; ++r) {
            float s = 0.0f;
            #pragma unroll
            for (int c = 0; c < 5; ++c)
                s = fmaf(hw2[c], sA2[c * 8 + r], s);
            t2[r] = s * dis;
        }
        float4* p = reinterpret_cast<float4*>(g_t2) + node * 2;
        p[0] = make_float4(t2[0], t2[1], t2[2], t2[3]);
        p[1] = make_float4(t2[4], t2[5], t2[6], t2[7]);
    }
}

// ---------------------------------------------------------------------------
// Launch 6: layer-2 gather + LoRA2-B + log_softmax; resets g_deg
__global__ void __launch_bounds__(256) k_out(const float* __restrict__ B2,
                                             float* __restrict__ out, int n) {
    __shared__ float sB2[40], sC[8];
    int tid = threadIdx.x;
    if (tid < 40) sB2[tid] = B2[tid];
    if (tid < 8)  sC[tid]  = g_cA2[tid];
    __syncthreads();

    int node = blockIdx.x * 128 + (tid >> 1);
    int q = tid & 1;
    float4 acc = make_float4(0.f, 0.f, 0.f, 0.f);
    if (node < n) {
        int off = g_off[node];
        int end = g_cur[node];
        acc = gather8(g_t2, off, end, q);
        float dis = g_dis[node];
        float4 h = *reinterpret_cast<const float4*>(&g_t2[node * 8 + q * 4]);
        acc.x = fmaf(dis, acc.x + h.x, sC[q * 4 + 0]);
        acc.y = fmaf(dis, acc.y + h.y, sC[q * 4 + 1]);
        acc.z = fmaf(dis, acc.z + h.z, sC[q * 4 + 2]);
        acc.w = fmaf(dis, acc.w + h.w, sC[q * 4 + 3]);
        if (q == 0) g_deg[node] = 0;     // restore invariant for next call
    }
    float4 o;
    o.x = __shfl_xor_sync(0xFFFFFFFFu, acc.x, 1);
    o.y = __shfl_xor_sync(0xFFFFFFFFu, acc.y, 1);
    o.z = __shfl_xor_sync(0xFFFFFFFFu, acc.z, 1);
    o.w = __shfl_xor_sync(0xFFFFFFFFu, acc.w, 1);
    if (node < n && q == 0) {
        float a[8] = {acc.x, acc.y, acc.z, acc.w, o.x, o.y, o.z, o.w};
        float l[5];
        float m = -1e30f;
        #pragma unroll
        for (int c = 0; c < 5; ++c) {
            float s = 0.0f;
            #pragma unroll
            for (int r = 0; r < 8; ++r)
                s = fmaf(a[r], sB2[r * 5 + c], s);
            l[c] = s * 0.125f;
            m = fmaxf(m, l[c]);
        }
        float se = 0.0f;
        #pragma unroll
        for (int c = 0; c < 5; ++c) se += expf(l[c] - m);
        float lse = m + logf(se);
        #pragma unroll
        for (int c = 0; c < 5; ++c)
            out[node * 5 + c] = l[c] - lse;
    }
}

// ---------------------------------------------------------------------------
extern "C" void kernel_launch(void* const* d_in, const int* in_sizes, int n_in,
                              void* d_out, int out_size) {
    const float* x    = (const float*)d_in[0];
    const int*   ei   = (const int*)  d_in[1];
    const int*   dom  = (const int*)  d_in[2];
    const float* emb  = (const float*)d_in[3];
    const float* W1   = (const float*)d_in[4];
    const float* b1   = (const float*)d_in[5];
    const float* A1   = (const float*)d_in[6];
    const float* B1   = (const float*)d_in[7];
    const float* W2   = (const float*)d_in[8];
    const float* b2   = (const float*)d_in[9];
    const float* A2   = (const float*)d_in[10];
    const float* B2   = (const float*)d_in[11];
    float* out = (float*)d_out;

    int N = in_sizes[2];
    int E = in_sizes[1] / 2;
    const int* src = ei;
    const int* dst = ei + E;

    int nbScan = (N + SCAN_B - 1) / SCAN_B;
    int nbAgg  = (N + 127) / 128;
    int nbS2   = (N + 255) / 256;                 // scan2 blocks (256 nodes each)
    int nbT1   = (N + 127) / 128;                 // t1 blocks (128 nodes each)
    int ebVec  = (E + 4 * 256 - 1) / (4 * 256);   // 4 edges/thread

    k_pre        <<<32 + ebVec, 256>>>(dst, emb, W1, E);
    k_scan1_prep <<<nbScan + 1, SCAN_B>>>(W1, A1, b1, A2, b2, N);
    k_scan2_t1   <<<nbS2 + nbT1, 256>>>(x, dom, N, nbS2);
    k_scatter    <<<ebVec, 256>>>(src, dst, E);
    k_agg1mid    <<<nbAgg, 256>>>(B1, W2, A2, N);
    k_out        <<<nbAgg, 256>>>(B2, out, N);
}